// round 1
// baseline (speedup 1.0000x reference)
#include <cuda_runtime.h>
#include <type_traits>

namespace plp {

constexpr int NBINS          = 257;   // fp32 bins per row (0..256)
constexpr int N_CH           = 40;
constexpr int ORDER          = 16;
constexpr int ROWS_PER_WARP  = 32;
constexpr int WARP_FLOATS    = ROWS_PER_WARP * NBINS;   // 8224
constexpr int WARPS_PER_BLK  = 2;
constexpr int BLOCK          = WARPS_PER_BLK * 32;

// ---------------- compile-time double-precision math ----------------
constexpr double cexp(double x) {            // |x| <= ~3
    double s = 1.0, t = 1.0;
    for (int k = 1; k < 60; ++k) { t = t * x / k; s += t; }
    return s;
}
constexpr double cln(double x) {             // x in (0, ~16)
    int n = 0;
    while (x > 1.3333333333333333) { x *= 0.5; ++n; }
    while (x < 0.75)               { x *= 2.0; --n; }
    double t = (x - 1.0) / (x + 1.0), t2 = t * t, s = 0.0, p = t;
    for (int k = 0; k < 40; ++k) { s += p / (2 * k + 1); p *= t2; }
    return 2.0 * s + n * 0.69314718055994530941723212145818;
}
constexpr double ccos(double x) {
    while (x >  3.14159265358979323846) x -= 6.28318530717958647692528676656;
    while (x < -3.14159265358979323846) x += 6.28318530717958647692528676656;
    double x2 = x * x, s = 1.0, t = 1.0;
    for (int k = 1; k < 30; ++k) { t *= -x2 / ((2.0 * k - 1.0) * (2.0 * k)); s += t; }
    return s;
}
constexpr double csin(double x) {            // |x| < pi
    double x2 = x * x, s = x, t = x;
    for (int k = 1; k < 30; ++k) { t *= -x2 / ((2.0 * k) * (2.0 * k + 1.0)); s += t; }
    return s;
}

// ---------------- all problem constants, built at compile time ----------------
struct Tables {
    int   chlo[256]; float wlo[256];   // bin b contributes wlo to channel chlo (if >=0)
    int   chhi[256]; float whi[256];   // and whi to channel chhi (if >=0)
    float eql[N_CH];
    float C[N_CH][ORDER + 1];          // r = y * C  (hfft of symmetric 42-pt extension, /82)
    float lift[ORDER];
};

constexpr Tables build() {
    Tables T{};
    const double mel_max = 1127.0 * cln(1.0 + 8000.0 / 700.0);
    const double d = mel_max / 41.0;
    double cf[41]{};   for (int s = 0; s < 41; ++s) cf[s] = d * (s + 1);
    double diff[41]{}; diff[0] = cf[0];
    for (int i = 1; i < 41; ++i) diff[i] = cf[i] - cf[i - 1];

    for (int b = 1; b < 256; ++b) {
        const double mel = 1127.0 * cln(1.0 + (31.25 * b) / 700.0);
        int ch = 0;
        for (int s = 0; s < 41; ++s) if (cf[s] < mel) ++ch;   // searchsorted 'left'
        const double w = (cf[ch] - mel) / diff[ch];
        T.chlo[b] = ch - 1;                 T.wlo[b] = (float)w;
        T.chhi[b] = (ch <= 39) ? ch : -1;   T.whi[b] = (float)(1.0 - w);
    }
    for (int c = 0; c < N_CH; ++c) {
        const double fhz = 700.0 * (cexp(cf[c] / 1127.0) - 1.0);
        const double f2  = fhz * fhz;
        T.eql[c] = (float)((f2 / (f2 + 160000.0)) * (f2 / (f2 + 160000.0))
                           * (f2 + 1440000.0) / (f2 + 9610000.0));
    }
    for (int j = 0; j < N_CH; ++j)
        for (int k = 0; k <= ORDER; ++k) {
            double v = 2.0 * ccos(6.28318530717958647692528676656
                                  * (double)((j + 1) * k) / 82.0);
            if (j == 0)  v += 1.0;
            if (j == 39) v += ((k & 1) ? -1.0 : 1.0);
            T.C[j][k] = (float)(v / 82.0);
        }
    for (int m = 1; m <= ORDER; ++m)
        T.lift[m - 1] = (float)(1.0 + 11.0 * csin(3.14159265358979323846 * m / 22.0));
    return T;
}
constexpr Tables TB = build();

// ---------------- compile-time for-loop (forces immediate folding) ----------------
template <int I, int N> struct SF {
    template <class F>
    __device__ __forceinline__ static void run(F&& f) {
        f(std::integral_constant<int, I>{});
        SF<I + 1, N>::run((F&&)f);
    }
};
template <int N> struct SF<N, N> {
    template <class F> __device__ __forceinline__ static void run(F&&) {}
};

__global__ void __launch_bounds__(BLOCK)
plp_kernel(const float* __restrict__ x, float* __restrict__ out, int nWarpsTotal) {
    extern __shared__ float xs[];
    const int lane = threadIdx.x & 31;
    const int wInB = threadIdx.x >> 5;
    const long long warpG = (long long)blockIdx.x * WARPS_PER_BLK + wInB;
    if (warpG >= nWarpsTotal) return;

    float* xw = xs + wInB * WARP_FLOATS;

    // ---- coalesced global -> shared copy of 32 rows (8224 floats, 16B aligned) ----
    const float4* g4 = reinterpret_cast<const float4*>(x + warpG * (long long)WARP_FLOATS);
    float4*       s4 = reinterpret_cast<float4*>(xw);
    #pragma unroll
    for (int i = 0; i < WARP_FLOATS / 4 / 32; ++i)       // 64 iters -> 2048 float4
        s4[lane + 32 * i] = g4[lane + 32 * i];
    if (lane < (WARP_FLOATS / 4 - (WARP_FLOATS / 4 / 32) * 32))   // remaining 8
        s4[(WARP_FLOATS / 4 / 32) * 32 + lane] = g4[(WARP_FLOATS / 4 / 32) * 32 + lane];
    __syncwarp();

    // ---- each lane owns one row; stride 257 (odd) => bank-conflict-free ----
    const float* xr = xw + lane * NBINS;

    float fb[N_CH];
    SF<0, N_CH>::run([&](auto c) { fb[c.value] = 0.f; });

    // triangular mel filterbank, weights as FFMA immediates
    SF<1, 256>::run([&](auto bc) {
        constexpr int b = bc.value;
        const float xv = xr[b];
        constexpr int clo = TB.chlo[b];
        constexpr int chi = TB.chhi[b];
        if constexpr (clo >= 0) { constexpr float w = TB.wlo[b]; fb[clo] = fmaf(w, xv, fb[clo]); }
        if constexpr (chi >= 0) { constexpr float w = TB.whi[b]; fb[chi] = fmaf(w, xv, fb[chi]); }
    });

    // equal-loudness + cube-root-ish compression
    float y[N_CH];
    SF<0, N_CH>::run([&](auto cc_) {
        constexpr int c = cc_.value;
        constexpr float e = TB.eql[c];
        const float v = fmaxf(fb[c], 1e-5f) * e;
        y[c] = powf(v, 0.33f);
    });

    // autocorrelation via cosine transform: r = y * C (immediates)
    float r[ORDER + 1];
    SF<0, ORDER + 1>::run([&](auto kc) { r[kc.value] = 0.f; });
    SF<0, N_CH>::run([&](auto jc) {
        constexpr int j = jc.value;
        const float yv = y[j];
        SF<0, ORDER + 1>::run([&](auto kc) {
            constexpr int k = kc.value;
            constexpr float cjk = TB.C[j][k];
            r[k] = fmaf(cjk, yv, r[k]);
        });
    });

    // ---- Levinson-Durbin (order 16), fully in registers ----
    float A[ORDER];
    float E = r[0];
    #pragma unroll
    for (int i = 1; i <= ORDER; ++i) {
        float acc = r[i];
        #pragma unroll
        for (int j = 1; j < i; ++j) acc += A[j - 1] * r[i - j];
        const float kk = -acc / E;
        #pragma unroll
        for (int j = 0; j < (i - 1) / 2; ++j) {
            const float t = A[j];
            A[j]         = t + kk * A[i - 2 - j];
            A[i - 2 - j] = A[i - 2 - j] + kk * t;
        }
        if (((i - 1) & 1) == 1) {
            const int mid = (i - 2) / 2;
            A[mid] = A[mid] + kk * A[mid];
        }
        A[i - 1] = kk;
        E = E * (1.0f - kk * kk);
    }

    // ---- LPC -> cepstrum ----
    float cst[ORDER + 1];
    cst[0] = logf(sqrtf(E));
    #pragma unroll
    for (int m = 1; m <= ORDER; ++m) {
        float acc = A[m - 1];
        #pragma unroll
        for (int k2 = 1; k2 < m; ++k2) {
            const float ratio = (float)k2 / (float)m;   // folds to immediate
            acc += ratio * cst[k2] * A[m - k2 - 1];
        }
        cst[m] = -acc;
    }

    // ---- lifter + store (warp writes 2KB contiguous) ----
    float o[ORDER];
    SF<0, ORDER>::run([&](auto ic) {
        constexpr int i = ic.value;
        constexpr float lf = TB.lift[i];
        o[i] = cst[i + 1] * lf;
    });

    const long long row = warpG * ROWS_PER_WARP + lane;
    float4* o4 = reinterpret_cast<float4*>(out + row * 16);
    o4[0] = make_float4(o[0],  o[1],  o[2],  o[3]);
    o4[1] = make_float4(o[4],  o[5],  o[6],  o[7]);
    o4[2] = make_float4(o[8],  o[9],  o[10], o[11]);
    o4[3] = make_float4(o[12], o[13], o[14], o[15]);
}

} // namespace plp

extern "C" void kernel_launch(void* const* d_in, const int* in_sizes, int n_in,
                              void* d_out, int out_size) {
    const float* x = (const float*)d_in[0];
    float* out = (float*)d_out;

    const int rows   = in_sizes[0] / plp::NBINS;          // 131072
    const int nWarps = rows / plp::ROWS_PER_WARP;         // 4096
    const int grid   = (nWarps + plp::WARPS_PER_BLK - 1) / plp::WARPS_PER_BLK;
    const int smem   = plp::WARPS_PER_BLK * plp::WARP_FLOATS * (int)sizeof(float); // 65792

    cudaFuncSetAttribute(plp::plp_kernel,
                         cudaFuncAttributeMaxDynamicSharedMemorySize, smem);
    plp::plp_kernel<<<grid, plp::BLOCK, smem>>>(x, out, nWarps);
}

// round 2
// speedup vs baseline: 1.2335x; 1.2335x over previous
#include <cuda_runtime.h>
#include <type_traits>

namespace plp {

constexpr int NBINS          = 257;
constexpr int N_CH           = 40;
constexpr int ORDER          = 16;
constexpr int ROWS_PER_WARP  = 32;
constexpr int WARP_FLOATS    = ROWS_PER_WARP * NBINS;   // 8224
constexpr int CB             = 32;                      // bins per chunk
constexpr int NCHUNK         = 8;                       // bins 0..255 staged
constexpr int WARPS_PER_BLK  = 4;
constexpr int BLOCK          = WARPS_PER_BLK * 32;
constexpr int SROW           = CB + 1;                  // 33, pad for conflict-free

// ---------------- compile-time double-precision math ----------------
constexpr double cexp(double x) {
    double s = 1.0, t = 1.0;
    for (int k = 1; k < 60; ++k) { t = t * x / k; s += t; }
    return s;
}
constexpr double cln(double x) {
    int n = 0;
    while (x > 1.3333333333333333) { x *= 0.5; ++n; }
    while (x < 0.75)               { x *= 2.0; --n; }
    double t = (x - 1.0) / (x + 1.0), t2 = t * t, s = 0.0, p = t;
    for (int k = 0; k < 40; ++k) { s += p / (2 * k + 1); p *= t2; }
    return 2.0 * s + n * 0.69314718055994530941723212145818;
}
constexpr double ccos(double x) {
    while (x >  3.14159265358979323846) x -= 6.28318530717958647692528676656;
    while (x < -3.14159265358979323846) x += 6.28318530717958647692528676656;
    double x2 = x * x, s = 1.0, t = 1.0;
    for (int k = 1; k < 30; ++k) { t *= -x2 / ((2.0 * k - 1.0) * (2.0 * k)); s += t; }
    return s;
}
constexpr double csin(double x) {
    double x2 = x * x, s = x, t = x;
    for (int k = 1; k < 30; ++k) { t *= -x2 / ((2.0 * k) * (2.0 * k + 1.0)); s += t; }
    return s;
}

// ---------------- all problem constants, built at compile time ----------------
struct Tables {
    int   chlo[256]; float wlo[256];
    int   chhi[256]; float whi[256];
    float eql[N_CH];
    float C[N_CH][ORDER + 1];
    float lift[ORDER];
};

constexpr Tables build() {
    Tables T{};
    const double mel_max = 1127.0 * cln(1.0 + 8000.0 / 700.0);
    const double d = mel_max / 41.0;
    double cf[41]{};   for (int s = 0; s < 41; ++s) cf[s] = d * (s + 1);
    double diff[41]{}; diff[0] = cf[0];
    for (int i = 1; i < 41; ++i) diff[i] = cf[i] - cf[i - 1];

    for (int b = 1; b < 256; ++b) {
        const double mel = 1127.0 * cln(1.0 + (31.25 * b) / 700.0);
        int ch = 0;
        for (int s = 0; s < 41; ++s) if (cf[s] < mel) ++ch;   // searchsorted 'left'
        const double w = (cf[ch] - mel) / diff[ch];
        T.chlo[b] = ch - 1;                 T.wlo[b] = (float)w;
        T.chhi[b] = (ch <= 39) ? ch : -1;   T.whi[b] = (float)(1.0 - w);
    }
    T.chlo[0] = -1; T.chhi[0] = -1;   // bin 0 unused
    for (int c = 0; c < N_CH; ++c) {
        const double fhz = 700.0 * (cexp(cf[c] / 1127.0) - 1.0);
        const double f2  = fhz * fhz;
        T.eql[c] = (float)((f2 / (f2 + 160000.0)) * (f2 / (f2 + 160000.0))
                           * (f2 + 1440000.0) / (f2 + 9610000.0));
    }
    for (int j = 0; j < N_CH; ++j)
        for (int k = 0; k <= ORDER; ++k) {
            double v = 2.0 * ccos(6.28318530717958647692528676656
                                  * (double)((j + 1) * k) / 82.0);
            if (j == 0)  v += 1.0;
            if (j == 39) v += ((k & 1) ? -1.0 : 1.0);
            T.C[j][k] = (float)(v / 82.0);
        }
    for (int m = 1; m <= ORDER; ++m)
        T.lift[m - 1] = (float)(1.0 + 11.0 * csin(3.14159265358979323846 * m / 22.0));
    return T;
}
constexpr Tables TB = build();

// ---------------- compile-time for-loop ----------------
template <int I, int N> struct SF {
    template <class F>
    __device__ __forceinline__ static void run(F&& f) {
        f(std::integral_constant<int, I>{});
        SF<I + 1, N>::run((F&&)f);
    }
};
template <int N> struct SF<N, N> {
    template <class F> __device__ __forceinline__ static void run(F&&) {}
};

__global__ void __launch_bounds__(BLOCK, 5)
plp_kernel(const float* __restrict__ x, float* __restrict__ out, int nWarpsTotal) {
    __shared__ float sbuf[WARPS_PER_BLK][ROWS_PER_WARP * SROW];   // 4 * 4224B

    const int lane = threadIdx.x & 31;
    const int wInB = threadIdx.x >> 5;
    const int warpG = blockIdx.x * WARPS_PER_BLK + wInB;
    if (warpG >= nWarpsTotal) return;

    float* s = sbuf[wInB];
    const float* gw = x + (long long)warpG * WARP_FLOATS;

    // ---- prefetch chunk 0 (bins 0..31) into registers: 32 coalesced LDGs ----
    float pre[ROWS_PER_WARP];
    #pragma unroll
    for (int i = 0; i < ROWS_PER_WARP; ++i)
        pre[i] = gw[i * NBINS + lane];

    float fb[N_CH];
    SF<0, N_CH>::run([&](auto c) { fb[c.value] = 0.f; });

    // ---- streamed filterbank: 8 chunks of 32 bins, prefetch-pipelined ----
    SF<0, NCHUNK>::run([&](auto cc) {
        constexpr int c = cc.value;
        // commit staged chunk to smem ((i+lane)%32: conflict-free)
        #pragma unroll
        for (int i = 0; i < ROWS_PER_WARP; ++i)
            s[i * SROW + lane] = pre[i];
        __syncwarp();
        // issue next chunk's loads NOW; they fly while we consume this chunk
        if constexpr (c < NCHUNK - 1) {
            #pragma unroll
            for (int i = 0; i < ROWS_PER_WARP; ++i)
                pre[i] = gw[i * NBINS + CB * (c + 1) + lane];
        }
        // consume: lane owns its row ((lane+j)%32: conflict-free)
        const float* xr = s + lane * SROW;
        SF<0, CB>::run([&](auto jc) {
            constexpr int j = jc.value;
            constexpr int b = CB * c + j;
            constexpr int clo = TB.chlo[b];
            constexpr int chi = TB.chhi[b];
            if constexpr (clo >= 0 || chi >= 0) {
                const float xv = xr[j];
                if constexpr (clo >= 0) { constexpr float w = TB.wlo[b]; fb[clo] = fmaf(w, xv, fb[clo]); }
                if constexpr (chi >= 0) { constexpr float w = TB.whi[b]; fb[chi] = fmaf(w, xv, fb[chi]); }
            }
        });
        __syncwarp();
    });

    // ---- equal-loudness + compression ----
    float y[N_CH];
    SF<0, N_CH>::run([&](auto cc_) {
        constexpr int c = cc_.value;
        constexpr float e = TB.eql[c];
        const float v = fmaxf(fb[c], 1e-5f) * e;
        y[c] = powf(v, 0.33f);
    });

    // ---- autocorrelation: r = y * C (immediates) ----
    float r[ORDER + 1];
    SF<0, ORDER + 1>::run([&](auto kc) { r[kc.value] = 0.f; });
    SF<0, N_CH>::run([&](auto jc) {
        constexpr int j = jc.value;
        const float yv = y[j];
        SF<0, ORDER + 1>::run([&](auto kc) {
            constexpr int k = kc.value;
            constexpr float cjk = TB.C[j][k];
            r[k] = fmaf(cjk, yv, r[k]);
        });
    });

    // ---- Levinson-Durbin (order 16) ----
    float A[ORDER];
    float E = r[0];
    #pragma unroll
    for (int i = 1; i <= ORDER; ++i) {
        float acc = r[i];
        #pragma unroll
        for (int j = 1; j < i; ++j) acc += A[j - 1] * r[i - j];
        const float kk = -acc / E;
        #pragma unroll
        for (int j = 0; j < (i - 1) / 2; ++j) {
            const float t = A[j];
            A[j]         = t + kk * A[i - 2 - j];
            A[i - 2 - j] = A[i - 2 - j] + kk * t;
        }
        if (((i - 1) & 1) == 1) {
            const int mid = (i - 2) / 2;
            A[mid] = A[mid] + kk * A[mid];
        }
        A[i - 1] = kk;
        E = E * (1.0f - kk * kk);
    }

    // ---- LPC -> cepstrum ----
    float cst[ORDER + 1];
    cst[0] = logf(sqrtf(E));
    #pragma unroll
    for (int m = 1; m <= ORDER; ++m) {
        float acc = A[m - 1];
        #pragma unroll
        for (int k2 = 1; k2 < m; ++k2) {
            const float ratio = (float)k2 / (float)m;
            acc += ratio * cst[k2] * A[m - k2 - 1];
        }
        cst[m] = -acc;
    }

    // ---- lifter + store ----
    float o[ORDER];
    SF<0, ORDER>::run([&](auto ic) {
        constexpr int i = ic.value;
        constexpr float lf = TB.lift[i];
        o[i] = cst[i + 1] * lf;
    });

    const long long row = (long long)warpG * ROWS_PER_WARP + lane;
    float4* o4 = reinterpret_cast<float4*>(out + row * 16);
    o4[0] = make_float4(o[0],  o[1],  o[2],  o[3]);
    o4[1] = make_float4(o[4],  o[5],  o[6],  o[7]);
    o4[2] = make_float4(o[8],  o[9],  o[10], o[11]);
    o4[3] = make_float4(o[12], o[13], o[14], o[15]);
}

} // namespace plp

extern "C" void kernel_launch(void* const* d_in, const int* in_sizes, int n_in,
                              void* d_out, int out_size) {
    const float* x = (const float*)d_in[0];
    float* out = (float*)d_out;

    const int rows   = in_sizes[0] / plp::NBINS;            // 131072
    const int nWarps = rows / plp::ROWS_PER_WARP;           // 4096
    const int grid   = (nWarps + plp::WARPS_PER_BLK - 1) / plp::WARPS_PER_BLK; // 1024

    plp::plp_kernel<<<grid, plp::BLOCK>>>(x, out, nWarps);
}

// round 3
// speedup vs baseline: 1.8183x; 1.4741x over previous
#include <cuda_runtime.h>
#include <type_traits>

namespace plp {

constexpr int NBINS          = 257;
constexpr int N_CH           = 40;
constexpr int ORDER          = 16;
constexpr int ROWS_PER_WARP  = 32;
constexpr int WARP_FLOATS    = ROWS_PER_WARP * NBINS;   // 8224
constexpr int CB             = 32;                      // bins per chunk
constexpr int NCHUNK         = 8;                       // bins 0..255 staged
constexpr int WARPS_PER_BLK  = 4;
constexpr int BLOCK          = WARPS_PER_BLK * 32;
constexpr int SROW           = CB + 1;                  // 33, pad for conflict-free

// ---------------- compile-time double-precision math ----------------
constexpr double cexp(double x) {
    double s = 1.0, t = 1.0;
    for (int k = 1; k < 60; ++k) { t = t * x / k; s += t; }
    return s;
}
constexpr double cln(double x) {
    int n = 0;
    while (x > 1.3333333333333333) { x *= 0.5; ++n; }
    while (x < 0.75)               { x *= 2.0; --n; }
    double t = (x - 1.0) / (x + 1.0), t2 = t * t, s = 0.0, p = t;
    for (int k = 0; k < 40; ++k) { s += p / (2 * k + 1); p *= t2; }
    return 2.0 * s + n * 0.69314718055994530941723212145818;
}
constexpr double ccos(double x) {
    while (x >  3.14159265358979323846) x -= 6.28318530717958647692528676656;
    while (x < -3.14159265358979323846) x += 6.28318530717958647692528676656;
    double x2 = x * x, s = 1.0, t = 1.0;
    for (int k = 1; k < 30; ++k) { t *= -x2 / ((2.0 * k - 1.0) * (2.0 * k)); s += t; }
    return s;
}
constexpr double csin(double x) {
    double x2 = x * x, s = x, t = x;
    for (int k = 1; k < 30; ++k) { t *= -x2 / ((2.0 * k) * (2.0 * k + 1.0)); s += t; }
    return s;
}

// ---------------- all problem constants, built at compile time ----------------
struct Tables {
    int   chlo[256]; float wlo[256];
    int   chhi[256]; float whi[256];
    float eql[N_CH];
    float C[N_CH][ORDER + 1];
    float lift[ORDER];
};

constexpr Tables build() {
    Tables T{};
    const double mel_max = 1127.0 * cln(1.0 + 8000.0 / 700.0);
    const double d = mel_max / 41.0;
    double cf[41]{};   for (int s = 0; s < 41; ++s) cf[s] = d * (s + 1);
    double diff[41]{}; diff[0] = cf[0];
    for (int i = 1; i < 41; ++i) diff[i] = cf[i] - cf[i - 1];

    for (int b = 1; b < 256; ++b) {
        const double mel = 1127.0 * cln(1.0 + (31.25 * b) / 700.0);
        int ch = 0;
        for (int s = 0; s < 41; ++s) if (cf[s] < mel) ++ch;   // searchsorted 'left'
        const double w = (cf[ch] - mel) / diff[ch];
        T.chlo[b] = ch - 1;                 T.wlo[b] = (float)w;
        T.chhi[b] = (ch <= 39) ? ch : -1;   T.whi[b] = (float)(1.0 - w);
    }
    T.chlo[0] = -1; T.chhi[0] = -1;   // bin 0 unused
    for (int c = 0; c < N_CH; ++c) {
        const double fhz = 700.0 * (cexp(cf[c] / 1127.0) - 1.0);
        const double f2  = fhz * fhz;
        T.eql[c] = (float)((f2 / (f2 + 160000.0)) * (f2 / (f2 + 160000.0))
                           * (f2 + 1440000.0) / (f2 + 9610000.0));
    }
    for (int j = 0; j < N_CH; ++j)
        for (int k = 0; k <= ORDER; ++k) {
            double v = 2.0 * ccos(6.28318530717958647692528676656
                                  * (double)((j + 1) * k) / 82.0);
            if (j == 0)  v += 1.0;
            if (j == 39) v += ((k & 1) ? -1.0 : 1.0);
            T.C[j][k] = (float)(v / 82.0);
        }
    for (int m = 1; m <= ORDER; ++m)
        T.lift[m - 1] = (float)(1.0 + 11.0 * csin(3.14159265358979323846 * m / 22.0));
    return T;
}
constexpr Tables TB = build();

// ---------------- compile-time for-loop ----------------
template <int I, int N> struct SF {
    template <class F>
    __device__ __forceinline__ static void run(F&& f) {
        f(std::integral_constant<int, I>{});
        SF<I + 1, N>::run((F&&)f);
    }
};
template <int N> struct SF<N, N> {
    template <class F> __device__ __forceinline__ static void run(F&&) {}
};

__global__ void __launch_bounds__(BLOCK, 5)
plp_kernel(const float* __restrict__ x, float* __restrict__ out, int nWarpsTotal) {
    __shared__ float sbuf[WARPS_PER_BLK][ROWS_PER_WARP * SROW];

    const int lane = threadIdx.x & 31;
    const int wInB = threadIdx.x >> 5;
    const int warpG = blockIdx.x * WARPS_PER_BLK + wInB;
    if (warpG >= nWarpsTotal) return;

    float* s = sbuf[wInB];
    const float* gw = x + (long long)warpG * WARP_FLOATS;

    // ---- prefetch chunk 0 (bins 0..31) into registers: 32 coalesced LDGs ----
    float pre[ROWS_PER_WARP];
    #pragma unroll
    for (int i = 0; i < ROWS_PER_WARP; ++i)
        pre[i] = gw[i * NBINS + lane];

    float fb[N_CH];
    SF<0, N_CH>::run([&](auto c) { fb[c.value] = 0.f; });

    // ---- streamed filterbank: 8 chunks of 32 bins, prefetch-pipelined ----
    SF<0, NCHUNK>::run([&](auto cc) {
        constexpr int c = cc.value;
        #pragma unroll
        for (int i = 0; i < ROWS_PER_WARP; ++i)
            s[i * SROW + lane] = pre[i];
        __syncwarp();
        if constexpr (c < NCHUNK - 1) {
            #pragma unroll
            for (int i = 0; i < ROWS_PER_WARP; ++i)
                pre[i] = gw[i * NBINS + CB * (c + 1) + lane];
        }
        const float* xr = s + lane * SROW;
        SF<0, CB>::run([&](auto jc) {
            constexpr int j = jc.value;
            constexpr int b = CB * c + j;
            constexpr int clo = TB.chlo[b];
            constexpr int chi = TB.chhi[b];
            if constexpr (clo >= 0 || chi >= 0) {
                const float xv = xr[j];
                if constexpr (clo >= 0) { constexpr float w = TB.wlo[b]; fb[clo] = fmaf(w, xv, fb[clo]); }
                if constexpr (chi >= 0) { constexpr float w = TB.whi[b]; fb[chi] = fmaf(w, xv, fb[chi]); }
            }
        });
        __syncwarp();
    });

    // ---- equal-loudness + compression: fast MUFU path ----
    // powf(v,0.33) == __expf(0.33*__logf(v)); MUFU lg2/ex2, ~2^-21 rel err
    float y[N_CH];
    SF<0, N_CH>::run([&](auto cc_) {
        constexpr int c = cc_.value;
        constexpr float e = TB.eql[c];
        const float v = fmaxf(fb[c], 1e-5f) * e;
        y[c] = __expf(0.33f * __logf(v));
    });

    // ---- autocorrelation: r = y * C (immediates) ----
    float r[ORDER + 1];
    SF<0, ORDER + 1>::run([&](auto kc) { r[kc.value] = 0.f; });
    SF<0, N_CH>::run([&](auto jc) {
        constexpr int j = jc.value;
        const float yv = y[j];
        SF<0, ORDER + 1>::run([&](auto kc) {
            constexpr int k = kc.value;
            constexpr float cjk = TB.C[j][k];
            r[k] = fmaf(cjk, yv, r[k]);
        });
    });

    // ---- Levinson-Durbin (order 16), fast reciprocal ----
    float A[ORDER];
    float E = r[0];
    #pragma unroll
    for (int i = 1; i <= ORDER; ++i) {
        float acc = r[i];
        #pragma unroll
        for (int j = 1; j < i; ++j) acc += A[j - 1] * r[i - j];
        const float kk = -__fdividef(acc, E);   // MUFU.RCP + mul
        #pragma unroll
        for (int j = 0; j < (i - 1) / 2; ++j) {
            const float t = A[j];
            A[j]         = t + kk * A[i - 2 - j];
            A[i - 2 - j] = A[i - 2 - j] + kk * t;
        }
        if (((i - 1) & 1) == 1) {
            const int mid = (i - 2) / 2;
            A[mid] = A[mid] + kk * A[mid];
        }
        A[i - 1] = kk;
        E = E * (1.0f - kk * kk);
    }

    // ---- LPC -> cepstrum ----
    float cst[ORDER + 1];
    cst[0] = 0.5f * __logf(E);          // log(sqrt(E))
    #pragma unroll
    for (int m = 1; m <= ORDER; ++m) {
        float acc = A[m - 1];
        #pragma unroll
        for (int k2 = 1; k2 < m; ++k2) {
            const float ratio = (float)k2 / (float)m;
            acc += ratio * cst[k2] * A[m - k2 - 1];
        }
        cst[m] = -acc;
    }

    // ---- lifter + store ----
    float o[ORDER];
    SF<0, ORDER>::run([&](auto ic) {
        constexpr int i = ic.value;
        constexpr float lf = TB.lift[i];
        o[i] = cst[i + 1] * lf;
    });

    const long long row = (long long)warpG * ROWS_PER_WARP + lane;
    float4* o4 = reinterpret_cast<float4*>(out + row * 16);
    o4[0] = make_float4(o[0],  o[1],  o[2],  o[3]);
    o4[1] = make_float4(o[4],  o[5],  o[6],  o[7]);
    o4[2] = make_float4(o[8],  o[9],  o[10], o[11]);
    o4[3] = make_float4(o[12], o[13], o[14], o[15]);
}

} // namespace plp

extern "C" void kernel_launch(void* const* d_in, const int* in_sizes, int n_in,
                              void* d_out, int out_size) {
    const float* x = (const float*)d_in[0];
    float* out = (float*)d_out;

    const int rows   = in_sizes[0] / plp::NBINS;            // 131072
    const int nWarps = rows / plp::ROWS_PER_WARP;           // 4096
    const int grid   = (nWarps + plp::WARPS_PER_BLK - 1) / plp::WARPS_PER_BLK; // 1024

    plp::plp_kernel<<<grid, plp::BLOCK>>>(x, out, nWarps);
}